// round 12
// baseline (speedup 1.0000x reference)
#include <cuda_runtime.h>
#include <math.h>
#include <stdint.h>

// ---------------------------------------------------------------------------
// CombinedElevationEncoder — conv1 bf16 mma, conv2 fp8 e4m3 m16n8k32 mma.
//
// Insight 1: dual-CNN branch only consumed through (4,4) block-mean pool ->
//            fuse conv1+relu+conv2+relu+pool; activations never touch GMEM.
// Insight 2: spiking LSTM emits spike(mem-1), mem = sig(o)*tanh(syn) <= 1
//            -> all spikes exactly 0 -> sconv_res == b_proj; scan skipped.
// R12: conv2 on fp8 (K=32 = 4 kw x 8 ic per MMA; 6 MMAs + 24 LDS per chunk
//     vs 9 + 36 bf16). conv1 epilogue packs e4m3 [pos][8 ic] directly.
//     32x128 tile, dyn smem 65.7KB, 2 CTAs/SM. Head = R7 8-way k-split.
// ---------------------------------------------------------------------------

#define BATCH 32
#define HH    128
#define WW    1536
#define TH    32
#define TW    128
#define GX    (WW / TW)  // 12
#define GY    (HH / TH)  // 4
#define NCONTRIB 3       // (32/TH)*(384/TW) = 1*3

#define IN_ROWS 38       // 32 out rows + 2 (conv2) + 4 (conv1) halo
#define IN_STR  152      // input tile cols (bf16x2 words, ic-interleaved)
#define C1_ROWS 34       // conv1 rows needed: out rows -1..+32
#define C1_STR  144      // conv1 plane cols (9 chunks of 16)
#define N_CH1   (C1_ROWS * 9)   // 306 conv1 chunks

// dynamic smem word offsets
#define OFF_INB 0                          // 38*152 = 5776
#define OFF_C1  5776                       // 34*144 pos * 2 words (fp8 [pos][8B])
#define OFF_W1B 15568                      // 320
#define OFF_W2F 15888                      // 384 (fp8 B table)
#define OFF_B1  16272
#define OFF_B2  16280
#define OFF_RED 16288                      // 128
#define SMEM_WORDS 16416
#define SMEM_BYTES (SMEM_WORDS * 4)        // 65664

// partial pooled sums: [b][oc][ph][pw][contrib]
__device__ float g_partial[BATCH * 8 * 4 * 4 * NCONTRIB];

// pack two fp32 -> bf16x2 (first arg = high half)
__device__ __forceinline__ uint32_t bfpack(float lo, float hi) {
    uint32_t d;
    asm("cvt.rn.bf16x2.f32 %0, %1, %2;" : "=r"(d) : "f"(hi), "f"(lo));
    return d;
}
// pack two fp32 -> e4m3x2 (16-bit; first asm operand = high byte)
__device__ __forceinline__ uint16_t e4pack2(float hi, float lo) {
    uint16_t d;
    asm("cvt.rn.satfinite.e4m3x2.f32 %0, %1, %2;" : "=h"(d) : "f"(hi), "f"(lo));
    return d;
}

// m16n8k16 bf16 mma, accumulate in place (fp32 accum)
__device__ __forceinline__ void mma_bf16(float& c0, float& c1, float& c2, float& c3,
                                         uint32_t a0, uint32_t a1, uint32_t a2, uint32_t a3,
                                         uint32_t b0, uint32_t b1) {
    asm volatile(
        "mma.sync.aligned.m16n8k16.row.col.f32.bf16.bf16.f32 "
        "{%0,%1,%2,%3}, {%4,%5,%6,%7}, {%8,%9}, {%0,%1,%2,%3};"
        : "+f"(c0), "+f"(c1), "+f"(c2), "+f"(c3)
        : "r"(a0), "r"(a1), "r"(a2), "r"(a3), "r"(b0), "r"(b1));
}
// m16n8k32 e4m3 mma, accumulate in place (fp32 accum)
__device__ __forceinline__ void mma_e4m3(float& c0, float& c1, float& c2, float& c3,
                                         uint32_t a0, uint32_t a1, uint32_t a2, uint32_t a3,
                                         uint32_t b0, uint32_t b1) {
    asm volatile(
        "mma.sync.aligned.m16n8k32.row.col.f32.e4m3.e4m3.f32 "
        "{%0,%1,%2,%3}, {%4,%5,%6,%7}, {%8,%9}, {%0,%1,%2,%3};"
        : "+f"(c0), "+f"(c1), "+f"(c2), "+f"(c3)
        : "r"(a0), "r"(a1), "r"(a2), "r"(a3), "r"(b0), "r"(b1));
}

// ---------------------------------------------------------------------------
__global__ __launch_bounds__(512, 2)
void conv_fused_kernel(const float* __restrict__ x,      // [B,2,H,W]
                       const float* __restrict__ w1,     // [8,2,5,7]
                       const float* __restrict__ b1,     // [8]
                       const float* __restrict__ w2,     // [8,8,3,5]
                       const float* __restrict__ b2)     // [8]
{
    extern __shared__ __align__(16) uint32_t dsm[];
    uint32_t* sInB = dsm + OFF_INB;   // [row38][col152] bf16x2 (ic0,ic1)
    uint32_t* sC1  = dsm + OFF_C1;    // fp8: [pos=row*144+c][8 ic bytes] = 2 words/pos
    uint32_t* sW1B = dsm + OFF_W1B;   // [(kh*8+kw)*8+oc] bf16x2
    uint32_t* sW2F = dsm + OFF_W2F;   // [((kh*8+kw8)*2+icq)*8+oc] e4m3x4
    float* sB1s = (float*)(dsm + OFF_B1);
    float* sB2s = (float*)(dsm + OFF_B2);
    float* sRed = (float*)(dsm + OFF_RED);

    const int tid = threadIdx.x;
    const int wid = tid >> 5;
    const int lid = tid & 31;
    const int g   = lid >> 2;     // fragment group
    const int tig = lid & 3;      // thread in group
    const int bx = blockIdx.x, by = blockIdx.y, b = blockIdx.z;
    const int h0 = by * TH - 3;
    const int w0 = bx * TW - 5;

    // ---- build conv1 weight table (bf16) ----
    for (int idx = tid; idx < 320; idx += 512) {
        int oc = idx & 7; int t = idx >> 3;
        int kw = t & 7; int kh = t >> 3;
        float lo = 0.f, hi = 0.f;
        if (kw < 7) {
            lo = w1[((oc * 2 + 0) * 5 + kh) * 7 + kw];
            hi = w1[((oc * 2 + 1) * 5 + kh) * 7 + kw];
        }
        sW1B[idx] = bfpack(lo, hi);
    }
    // ---- build conv2 weight table (e4m3): word = 4 ic bytes ----
    for (int idx = tid; idx < 384; idx += 512) {
        int oc = idx & 7; int t = idx >> 3;
        int icq = t & 1; t >>= 1;
        int kw8 = t & 7; int kh = t >> 3;
        float v[4];
        #pragma unroll
        for (int j = 0; j < 4; j++) {
            int ic = icq * 4 + j;
            v[j] = (kw8 < 5) ? w2[((oc * 8 + ic) * 3 + kh) * 5 + kw8] : 0.f;
        }
        uint32_t lo16 = e4pack2(v[1], v[0]);
        uint32_t hi16 = e4pack2(v[3], v[2]);
        sW2F[idx] = lo16 | (hi16 << 16);
    }
    if (tid < 8) { sB1s[tid] = b1[tid]; sB2s[tid] = b2[tid]; }

    // ---- load input tile, ic-interleaved bf16 (spikes 0/1 -> exact) ----
    const float* xb = x + (size_t)b * 2 * HH * WW;
    for (int idx = tid; idx < IN_ROWS * IN_STR; idx += 512) {
        int col = idx % IN_STR, row = idx / IN_STR;
        int gh = h0 + row, gw = w0 + col;
        float v0 = 0.f, v1 = 0.f;
        if (gh >= 0 && gh < HH && gw >= 0 && gw < WW) {
            v0 = xb[gh * WW + gw];
            v1 = xb[HH * WW + gh * WW + gw];
        }
        sInB[idx] = bfpack(v0, v1);
    }
    __syncthreads();

    // ---- conv1 via bf16 mma: 306 chunks; epilogue packs e4m3 [pos][8 ic] ----
    {
        uint32_t bf[10];
        #pragma unroll
        for (int kh = 0; kh < 5; kh++) {
            bf[kh * 2]     = sW1B[(kh * 8 + tig)     * 8 + g];
            bf[kh * 2 + 1] = sW1B[(kh * 8 + tig + 4) * 8 + g];
        }
        const float bi0 = sB1s[2 * tig], bi1 = sB1s[2 * tig + 1];
        const uint32_t c1base = (uint32_t)__cvta_generic_to_shared(sC1);

        for (int cc = wid; cc < N_CH1; cc += 16) {
            const int r  = cc / 9;
            const int c0 = (cc % 9) * 16;
            float d0 = bi0, d1 = bi1, d2 = bi0, d3 = bi1;
            #pragma unroll
            for (int kh = 0; kh < 5; kh++) {
                const uint32_t* rp = &sInB[(r + kh) * IN_STR + c0];
                uint32_t a0 = rp[g + tig];            // m=g,   kw=tig
                uint32_t a1 = rp[g + 8 + tig];        // m=g+8
                uint32_t a2 = rp[g + tig + 4];        // kw=tig+4
                uint32_t a3 = rp[g + 8 + tig + 4];
                mma_bf16(d0, d1, d2, d3, a0, a1, a2, a3,
                         bf[kh * 2], bf[kh * 2 + 1]);
            }
            // relu + e4m3 pack; thread holds oc (2tig, 2tig+1) at pos g, g+8
            const int pos0 = r * C1_STR + c0 + g;
            uint16_t p0 = e4pack2(fmaxf(d1, 0.f), fmaxf(d0, 0.f));
            uint16_t p1 = e4pack2(fmaxf(d3, 0.f), fmaxf(d2, 0.f));
            asm volatile("st.shared.u16 [%0], %1;"
                         :: "r"(c1base + (uint32_t)(pos0 * 8 + 2 * tig)), "h"(p0) : "memory");
            asm volatile("st.shared.u16 [%0], %1;"
                         :: "r"(c1base + (uint32_t)((pos0 + 8) * 8 + 2 * tig)), "h"(p1) : "memory");
        }
    }
    __syncthreads();

    // ---- conv2 via fp8 mma + pool partial: warp = rows wid, wid+16 ----
    {
        // B frags: slot = kh*2 + h; b0 kw8 = h*4+(tig>>1), b1 kw8 = +2
        uint32_t bw[12];
        #pragma unroll
        for (int kh = 0; kh < 3; kh++)
            #pragma unroll
            for (int h = 0; h < 2; h++) {
                bw[(kh * 2 + h) * 2] =
                    sW2F[((kh * 8 + h * 4 + (tig >> 1)) * 2 + (tig & 1)) * 8 + g];
                bw[(kh * 2 + h) * 2 + 1] =
                    sW2F[((kh * 8 + h * 4 + 2 + (tig >> 1)) * 2 + (tig & 1)) * 8 + g];
            }
        const float bi0 = sB2s[2 * tig], bi1 = sB2s[2 * tig + 1];

        float s0 = 0.f, s1 = 0.f;
        #pragma unroll
        for (int rr = 0; rr < 2; rr++) {
            const int row = wid + rr * 16;      // out rows 0..31
            #pragma unroll
            for (int ch = 0; ch < 8; ch++) {
                const int c0 = ch * 16;
                float d0 = bi0, d1 = bi1, d2 = bi0, d3 = bi1;
                #pragma unroll
                for (int kh = 0; kh < 3; kh++) {
                    const int posb = (row + kh) * C1_STR + c0;
                    #pragma unroll
                    for (int h = 0; h < 2; h++) {
                        // a0: pos = posb + h*4 + (tig>>1) + g, word half (tig&1)
                        const int pb = posb + h * 4 + (tig >> 1) + g;
                        uint32_t a0 = sC1[(pb)      * 2 + (tig & 1)];
                        uint32_t a1 = sC1[(pb + 8)  * 2 + (tig & 1)];
                        uint32_t a2 = sC1[(pb + 2)  * 2 + (tig & 1)];
                        uint32_t a3 = sC1[(pb + 10) * 2 + (tig & 1)];
                        mma_e4m3(d0, d1, d2, d3, a0, a1, a2, a3,
                                 bw[(kh * 2 + h) * 2], bw[(kh * 2 + h) * 2 + 1]);
                    }
                }
                s0 += fmaxf(d0, 0.f) + fmaxf(d2, 0.f);
                s1 += fmaxf(d1, 0.f) + fmaxf(d3, 0.f);
            }
        }
        // reduce over g (lane bits 2..4); s0 = oc 2tig, s1 = oc 2tig+1
        #pragma unroll
        for (int off = 4; off <= 16; off <<= 1) {
            s0 += __shfl_xor_sync(0xffffffffu, s0, off);
            s1 += __shfl_xor_sync(0xffffffffu, s1, off);
        }
        if (lid < 4) {
            sRed[wid * 8 + 2 * tig]     = s0;
            sRed[wid * 8 + 2 * tig + 1] = s1;
        }
    }
    __syncthreads();

    // deterministic partial write: one fixed slot per block (no atomics)
    if (tid < 8) {
        float t = 0.f;
        #pragma unroll
        for (int wz = 0; wz < 16; wz++) t += sRed[wz * 8 + tid];
        const int ph = by;                          // 1 row-tile per pool cell
        const int pw = bx / 3,  subx = bx - pw * 3; // 3 col-tiles per pool cell
        g_partial[(((b * 8 + tid) * 4 + ph) * 4 + pw) * NCONTRIB + subx] = t;
    }
}

// ---------------------------------------------------------------------------
// Head: grid (24, 32). seg -> branch (seg>>3) and 64-col segment (seg&7).
// 256 thr = 8 ks x 32 jq; jq owns 2 cols. sconv branch == b_proj.
// ---------------------------------------------------------------------------
__global__ __launch_bounds__(256)
void head_kernel(const float* __restrict__ distance,
                 const float* __restrict__ azimuth,
                 const float* __restrict__ elevation,
                 const float* __restrict__ W_dist, const float* __restrict__ b_dist,
                 const float* __restrict__ W_az,   const float* __restrict__ b_az,
                 const float* __restrict__ W_el,   const float* __restrict__ b_el,
                 const float* __restrict__ W_res,  const float* __restrict__ b_res,
                 const float* __restrict__ b_proj,
                 const float* __restrict__ cnn_gain,
                 const float* __restrict__ sconv_gain,
                 float* __restrict__ out)
{
    __shared__ float sv[256];
    __shared__ float sp[128];
    __shared__ float2 sacc[8][32];
    __shared__ float2 slr[8][32];

    const int tid = threadIdx.x;
    const int jq  = tid & 31;
    const int ks  = tid >> 5;          // 0..7
    const int b   = blockIdx.y;
    const int seg = blockIdx.x;        // 0..23
    const int branch = seg >> 3;       // uniform per block
    const int j = (seg & 7) * 64 + jq * 2;   // col within 512

    const float* vec = (branch == 0) ? distance : (branch == 1) ? azimuth : elevation;
    sv[tid] = vec[b * 256 + tid];

    if (branch == 2 && tid < 128) {
        const float* pp = g_partial + (b * 128 + tid) * NCONTRIB;
        float t = 0.f;
        #pragma unroll
        for (int i = 0; i < NCONTRIB; i++) t += pp[i];
        sp[tid] = t * (1.0f / (32.0f * 384.0f));
    }
    __syncthreads();

    const float* Wm = (branch == 0) ? W_dist : (branch == 1) ? W_az : W_el;
    float2 acc = make_float2(0.f, 0.f);
    #pragma unroll 8
    for (int k = ks * 32; k < ks * 32 + 32; k++) {
        float s = sv[k];
        float2 w = *(const float2*)&Wm[k * 512 + j];
        acc.x = fmaf(s, w.x, acc.x);
        acc.y = fmaf(s, w.y, acc.y);
    }
    sacc[ks][jq] = acc;

    if (branch == 2) {
        float2 lr = make_float2(0.f, 0.f);
        #pragma unroll 8
        for (int k = ks * 16; k < ks * 16 + 16; k++) {
            float s = sp[k];
            float2 w = *(const float2*)&W_res[k * 512 + j];
            lr.x = fmaf(s, w.x, lr.x);
            lr.y = fmaf(s, w.y, lr.y);
        }
        slr[ks][jq] = lr;
    }
    __syncthreads();

    if (ks == 0) {
        float rx = 0.f, ry = 0.f;
        #pragma unroll
        for (int p = 0; p < 8; p++) { rx += sacc[p][jq].x; ry += sacc[p][jq].y; }

        float2 r;
        if (branch == 0) {
            r.x = fmaxf(rx + b_dist[j],     0.f);
            r.y = fmaxf(ry + b_dist[j + 1], 0.f);
        } else if (branch == 1) {
            r.x = fmaxf(rx + b_az[j],     0.f);
            r.y = fmaxf(ry + b_az[j + 1], 0.f);
        } else {
            float bx0 = fmaxf(rx + b_el[j],     0.f);
            float by0 = fmaxf(ry + b_el[j + 1], 0.f);
            float lx = 0.f, ly = 0.f;
            #pragma unroll
            for (int p = 0; p < 8; p++) { lx += slr[p][jq].x; ly += slr[p][jq].y; }
            lx += b_res[j]; ly += b_res[j + 1];
            float cs = 0.5f / (1.0f + expf(-cnn_gain[0]));
            float ss = 0.4f / (1.0f + expf(-sconv_gain[0]));
            r.x = fmaxf(bx0 + cs * lx + ss * b_proj[j],     0.f);
            r.y = fmaxf(by0 + cs * ly + ss * b_proj[j + 1], 0.f);
        }
        *(float2*)&out[b * 1536 + branch * 512 + j] = r;
    }
}

// ---------------------------------------------------------------------------
extern "C" void kernel_launch(void* const* d_in, const int* in_sizes, int n_in,
                              void* d_out, int out_size)
{
    const float* distance   = (const float*)d_in[0];
    const float* azimuth    = (const float*)d_in[1];
    const float* elevation  = (const float*)d_in[2];
    const float* rspikes    = (const float*)d_in[3];
    const float* W_dist     = (const float*)d_in[4];
    const float* b_dist     = (const float*)d_in[5];
    const float* W_az       = (const float*)d_in[6];
    const float* b_az       = (const float*)d_in[7];
    const float* W_el       = (const float*)d_in[8];
    const float* b_el       = (const float*)d_in[9];
    const float* conv1_w    = (const float*)d_in[10];
    const float* conv1_b    = (const float*)d_in[11];
    const float* conv2_w    = (const float*)d_in[12];
    const float* conv2_b    = (const float*)d_in[13];
    const float* W_res      = (const float*)d_in[14];
    const float* b_res      = (const float*)d_in[15];
    const float* b_proj     = (const float*)d_in[19];
    const float* cnn_gain   = (const float*)d_in[20];
    const float* sconv_gain = (const float*)d_in[21];

    cudaFuncSetAttribute(conv_fused_kernel,
                         cudaFuncAttributeMaxDynamicSharedMemorySize, SMEM_BYTES);

    dim3 gconv(GX, GY, BATCH);
    conv_fused_kernel<<<gconv, 512, SMEM_BYTES>>>(rspikes, conv1_w, conv1_b,
                                                  conv2_w, conv2_b);

    dim3 ghead(24, BATCH);
    head_kernel<<<ghead, 256>>>(distance, azimuth, elevation,
                                W_dist, b_dist, W_az, b_az, W_el, b_el,
                                W_res, b_res, b_proj, cnn_gain, sconv_gain,
                                (float*)d_out);
}

// round 13
// speedup vs baseline: 1.2329x; 1.2329x over previous
#include <cuda_runtime.h>
#include <math.h>
#include <stdint.h>

// ---------------------------------------------------------------------------
// CombinedElevationEncoder — both convs on bf16 m16n8k16 mma.sync.
//
// Insight 1: dual-CNN branch only consumed through (4,4) block-mean pool ->
//            fuse conv1+relu+conv2+relu+pool; activations never touch GMEM.
// Insight 2: spiking LSTM emits spike(mem-1), mem = sig(o)*tanh(syn) <= 1
//            -> all spikes exactly 0 -> sconv_res == b_proj; scan skipped.
// R13: revert fp8 (R12 regressed: legacy fp8 MMA rate + cvt/u16-store cost).
//     R11 base + (a) conv1 row-pair units sharing 4/5 A-fragment rows
//     (380 -> ~240 LDS/warp, identical MMA chains), (b) aligned float4 input
//     loader (w0 = bx*128-8 so every quad is 16B-aligned and fully in/out).
//     Head = R7 8-way k-split.
// ---------------------------------------------------------------------------

#define BATCH 32
#define HH    128
#define WW    1536
#define TH    32
#define TW    128
#define GX    (WW / TW)  // 12
#define GY    (HH / TH)  // 4
#define NCONTRIB 3       // (32/TH)*(384/TW) = 1*3

#define IN_ROWS 38       // 32 out rows + 2 (conv2) + 4 (conv1) halo
#define IN_STR  160      // input tile cols (bf16x2 words); quad-aligned
#define C1_ROWS 34       // conv1 rows needed: out rows -1..+32
#define C1_STR  144      // conv1 plane cols (9 chunks of 16)
#define N_UNITS 153      // conv1 row-pair units: 9 strips * 17 pairs

// dynamic smem word offsets
#define OFF_INB 0                          // 38*160 = 6080
#define OFF_C1  6080                       // 34*144*4 = 19584 (byte 24320, 16B ok)
#define OFF_W1B 25664                      // 320
#define OFF_W2B 25984                      // 576
#define OFF_B1  26560
#define OFF_B2  26568
#define OFF_RED 26576                      // 128
#define SMEM_WORDS 26704
#define SMEM_BYTES (SMEM_WORDS * 4)        // 106816

// partial pooled sums: [b][oc][ph][pw][contrib]
__device__ float g_partial[BATCH * 8 * 4 * 4 * NCONTRIB];

// pack two fp32 -> bf16x2 (lo = first arg)
__device__ __forceinline__ uint32_t bfpack(float lo, float hi) {
    uint32_t d;
    asm("cvt.rn.bf16x2.f32 %0, %1, %2;" : "=r"(d) : "f"(hi), "f"(lo));
    return d;
}

// m16n8k16 bf16 mma, accumulate in place (fp32 accum)
__device__ __forceinline__ void mma_bf16(float& c0, float& c1, float& c2, float& c3,
                                         uint32_t a0, uint32_t a1, uint32_t a2, uint32_t a3,
                                         uint32_t b0, uint32_t b1) {
    asm volatile(
        "mma.sync.aligned.m16n8k16.row.col.f32.bf16.bf16.f32 "
        "{%0,%1,%2,%3}, {%4,%5,%6,%7}, {%8,%9}, {%0,%1,%2,%3};"
        : "+f"(c0), "+f"(c1), "+f"(c2), "+f"(c3)
        : "r"(a0), "r"(a1), "r"(a2), "r"(a3), "r"(b0), "r"(b1));
}

// ---------------------------------------------------------------------------
__global__ __launch_bounds__(512, 2)
void conv_fused_kernel(const float* __restrict__ x,      // [B,2,H,W]
                       const float* __restrict__ w1,     // [8,2,5,7]
                       const float* __restrict__ b1,     // [8]
                       const float* __restrict__ w2,     // [8,8,3,5]
                       const float* __restrict__ b2)     // [8]
{
    extern __shared__ __align__(16) uint32_t dsm[];
    uint32_t* sInB = dsm + OFF_INB;   // [row38][col160] bf16x2 (ic0,ic1)
    uint32_t* sC1  = dsm + OFF_C1;    // [pos=row*144+c][4 words: tig -> oc 2tig,2tig+1]
    uint32_t* sW1B = dsm + OFF_W1B;   // [(kh*8+kw)*8+oc]
    uint32_t* sW2B = dsm + OFF_W2B;   // [((kh*6+kw)*4+tg)*8+oc]
    float* sB1s = (float*)(dsm + OFF_B1);
    float* sB2s = (float*)(dsm + OFF_B2);
    float* sRed = (float*)(dsm + OFF_RED);

    const int tid = threadIdx.x;
    const int wid = tid >> 5;
    const int lid = tid & 31;
    const int g   = lid >> 2;     // fragment group
    const int tig = lid & 3;      // thread in group
    const int bx = blockIdx.x, by = blockIdx.y, b = blockIdx.z;
    const int h0 = by * TH - 3;
    const int w0 = bx * TW - 8;   // 4-aligned tile origin (input word col +3 shift)

    // ---- build weight tables ----
    for (int idx = tid; idx < 320; idx += 512) {
        int oc = idx & 7; int t = idx >> 3;
        int kw = t & 7; int kh = t >> 3;
        float lo = 0.f, hi = 0.f;
        if (kw < 7) {
            lo = w1[((oc * 2 + 0) * 5 + kh) * 7 + kw];
            hi = w1[((oc * 2 + 1) * 5 + kh) * 7 + kw];
        }
        sW1B[idx] = bfpack(lo, hi);
    }
    for (int idx = tid; idx < 576; idx += 512) {
        int oc = idx & 7; int t = idx >> 3;
        int tg = t & 3; t >>= 2;
        int kw = t % 6; int kh = t / 6;
        float lo = 0.f, hi = 0.f;
        if (kw < 5) {
            lo = w2[((oc * 8 + 2 * tg)     * 3 + kh) * 5 + kw];
            hi = w2[((oc * 8 + 2 * tg + 1) * 3 + kh) * 5 + kw];
        }
        sW2B[idx] = bfpack(lo, hi);
    }
    if (tid < 8) { sB1s[tid] = b1[tid]; sB2s[tid] = b2[tid]; }

    // ---- load input tile: aligned float4 quads, ic-interleaved bf16 ----
    // every quad is fully in-bounds or fully out (w0 % 4 == 0)
    {
        const float* p0 = x + (size_t)b * 2 * HH * WW;
        const float* p1 = p0 + HH * WW;
        for (int idx = tid; idx < IN_ROWS * 40; idx += 512) {
            int cq = idx % 40, row = idx / 40;
            int gh = h0 + row;
            int gw = w0 + cq * 4;
            float4 v0 = make_float4(0.f, 0.f, 0.f, 0.f);
            float4 v1 = v0;
            if (gh >= 0 && gh < HH && gw >= 0 && gw + 3 < WW) {
                v0 = *(const float4*)&p0[gh * WW + gw];
                v1 = *(const float4*)&p1[gh * WW + gw];
            }
            uint4 wv;
            wv.x = bfpack(v0.x, v1.x);
            wv.y = bfpack(v0.y, v1.y);
            wv.z = bfpack(v0.z, v1.z);
            wv.w = bfpack(v0.w, v1.w);
            *(uint4*)&sInB[row * IN_STR + cq * 4] = wv;
        }
    }
    __syncthreads();

    // ---- conv1 via mma: 153 row-pair units (9 strips x 17 pairs) ----
    // unit = (strip s, rows r0, r0+1); fragments for rows r0..r0+5 loaded once,
    // 4/5 shared between the two serial 5-MMA chains (identical to R11 math).
    {
        uint32_t bf[10];
        #pragma unroll
        for (int kh = 0; kh < 5; kh++) {
            bf[kh * 2]     = sW1B[(kh * 8 + tig)     * 8 + g];
            bf[kh * 2 + 1] = sW1B[(kh * 8 + tig + 4) * 8 + g];
        }
        const float bi0 = sB1s[2 * tig], bi1 = sB1s[2 * tig + 1];

        for (int u = wid; u < N_UNITS; u += 16) {
            const int s  = u / 17;
            const int r0 = (u % 17) * 2;
            const int ci = s * 16 + 3;          // input word base (+3 shift)

            uint32_t f[6][4];
            #pragma unroll
            for (int rr = 0; rr < 6; rr++) {
                const uint32_t* q = &sInB[(r0 + rr) * IN_STR + ci];
                f[rr][0] = q[g + tig];            // m=g,   kw=tig
                f[rr][1] = q[g + 8 + tig];        // m=g+8
                f[rr][2] = q[g + tig + 4];        // kw=tig+4
                f[rr][3] = q[g + 8 + tig + 4];
            }

            #pragma unroll
            for (int cr = 0; cr < 2; cr++) {
                float d0 = bi0, d1 = bi1, d2 = bi0, d3 = bi1;
                #pragma unroll
                for (int kh = 0; kh < 5; kh++)
                    mma_bf16(d0, d1, d2, d3,
                             f[cr + kh][0], f[cr + kh][1],
                             f[cr + kh][2], f[cr + kh][3],
                             bf[kh * 2], bf[kh * 2 + 1]);
                // relu + bf16 pack; C frag (oc pair at m=g, g+8) == conv2 A layout
                const int pos = (r0 + cr) * C1_STR + s * 16;
                sC1[(pos + g)     * 4 + tig] = bfpack(fmaxf(d0, 0.f), fmaxf(d1, 0.f));
                sC1[(pos + g + 8) * 4 + tig] = bfpack(fmaxf(d2, 0.f), fmaxf(d3, 0.f));
            }
        }
    }
    __syncthreads();

    // ---- conv2 via mma + pool partial: warp = rows wid, wid+16; 8 chunks ----
    {
        uint32_t bf[18];
        #pragma unroll
        for (int kh = 0; kh < 3; kh++)
            #pragma unroll
            for (int kw6 = 0; kw6 < 6; kw6++)
                bf[kh * 6 + kw6] = sW2B[((kh * 6 + kw6) * 4 + tig) * 8 + g];
        const float bi0 = sB2s[2 * tig], bi1 = sB2s[2 * tig + 1];

        float s0 = 0.f, s1 = 0.f;
        #pragma unroll
        for (int rr = 0; rr < 2; rr++) {
            const int row = wid + rr * 16;      // out rows 0..31
            #pragma unroll
            for (int ch = 0; ch < 8; ch++) {
                const int c0 = ch * 16;
                float d0 = bi0, d1 = bi1, d2 = bi0, d3 = bi1;
                #pragma unroll
                for (int kh = 0; kh < 3; kh++) {
                    #pragma unroll
                    for (int j = 0; j < 3; j++) {
                        const int kwb = 2 * j;
                        const uint32_t* pp = &sC1[((row + kh) * C1_STR + c0 + kwb) * 4];
                        uint32_t a0 = pp[(g)     * 4 + tig];   // kw=kwb,   m=g
                        uint32_t a1 = pp[(g + 8) * 4 + tig];   // m=g+8
                        uint32_t a2 = pp[(g + 1) * 4 + tig];   // kw=kwb+1
                        uint32_t a3 = pp[(g + 9) * 4 + tig];
                        mma_bf16(d0, d1, d2, d3, a0, a1, a2, a3,
                                 bf[kh * 6 + kwb], bf[kh * 6 + kwb + 1]);
                    }
                }
                s0 += fmaxf(d0, 0.f) + fmaxf(d2, 0.f);
                s1 += fmaxf(d1, 0.f) + fmaxf(d3, 0.f);
            }
        }
        // reduce over g (lane bits 2..4); s0 = oc 2tig, s1 = oc 2tig+1
        #pragma unroll
        for (int off = 4; off <= 16; off <<= 1) {
            s0 += __shfl_xor_sync(0xffffffffu, s0, off);
            s1 += __shfl_xor_sync(0xffffffffu, s1, off);
        }
        if (lid < 4) {
            sRed[wid * 8 + 2 * tig]     = s0;
            sRed[wid * 8 + 2 * tig + 1] = s1;
        }
    }
    __syncthreads();

    // deterministic partial write: one fixed slot per block (no atomics)
    if (tid < 8) {
        float t = 0.f;
        #pragma unroll
        for (int wz = 0; wz < 16; wz++) t += sRed[wz * 8 + tid];
        const int ph = by;                          // 1 row-tile per pool cell
        const int pw = bx / 3,  subx = bx - pw * 3; // 3 col-tiles per pool cell
        g_partial[(((b * 8 + tid) * 4 + ph) * 4 + pw) * NCONTRIB + subx] = t;
    }
}

// ---------------------------------------------------------------------------
// Head: grid (24, 32). seg -> branch (seg>>3) and 64-col segment (seg&7).
// 256 thr = 8 ks x 32 jq; jq owns 2 cols. sconv branch == b_proj.
// ---------------------------------------------------------------------------
__global__ __launch_bounds__(256)
void head_kernel(const float* __restrict__ distance,
                 const float* __restrict__ azimuth,
                 const float* __restrict__ elevation,
                 const float* __restrict__ W_dist, const float* __restrict__ b_dist,
                 const float* __restrict__ W_az,   const float* __restrict__ b_az,
                 const float* __restrict__ W_el,   const float* __restrict__ b_el,
                 const float* __restrict__ W_res,  const float* __restrict__ b_res,
                 const float* __restrict__ b_proj,
                 const float* __restrict__ cnn_gain,
                 const float* __restrict__ sconv_gain,
                 float* __restrict__ out)
{
    __shared__ float sv[256];
    __shared__ float sp[128];
    __shared__ float2 sacc[8][32];
    __shared__ float2 slr[8][32];

    const int tid = threadIdx.x;
    const int jq  = tid & 31;
    const int ks  = tid >> 5;          // 0..7
    const int b   = blockIdx.y;
    const int seg = blockIdx.x;        // 0..23
    const int branch = seg >> 3;       // uniform per block
    const int j = (seg & 7) * 64 + jq * 2;   // col within 512

    const float* vec = (branch == 0) ? distance : (branch == 1) ? azimuth : elevation;
    sv[tid] = vec[b * 256 + tid];

    if (branch == 2 && tid < 128) {
        const float* pp = g_partial + (b * 128 + tid) * NCONTRIB;
        float t = 0.f;
        #pragma unroll
        for (int i = 0; i < NCONTRIB; i++) t += pp[i];
        sp[tid] = t * (1.0f / (32.0f * 384.0f));
    }
    __syncthreads();

    const float* Wm = (branch == 0) ? W_dist : (branch == 1) ? W_az : W_el;
    float2 acc = make_float2(0.f, 0.f);
    #pragma unroll 8
    for (int k = ks * 32; k < ks * 32 + 32; k++) {
        float s = sv[k];
        float2 w = *(const float2*)&Wm[k * 512 + j];
        acc.x = fmaf(s, w.x, acc.x);
        acc.y = fmaf(s, w.y, acc.y);
    }
    sacc[ks][jq] = acc;

    if (branch == 2) {
        float2 lr = make_float2(0.f, 0.f);
        #pragma unroll 8
        for (int k = ks * 16; k < ks * 16 + 16; k++) {
            float s = sp[k];
            float2 w = *(const float2*)&W_res[k * 512 + j];
            lr.x = fmaf(s, w.x, lr.x);
            lr.y = fmaf(s, w.y, lr.y);
        }
        slr[ks][jq] = lr;
    }
    __syncthreads();

    if (ks == 0) {
        float rx = 0.f, ry = 0.f;
        #pragma unroll
        for (int p = 0; p < 8; p++) { rx += sacc[p][jq].x; ry += sacc[p][jq].y; }

        float2 r;
        if (branch == 0) {
            r.x = fmaxf(rx + b_dist[j],     0.f);
            r.y = fmaxf(ry + b_dist[j + 1], 0.f);
        } else if (branch == 1) {
            r.x = fmaxf(rx + b_az[j],     0.f);
            r.y = fmaxf(ry + b_az[j + 1], 0.f);
        } else {
            float bx0 = fmaxf(rx + b_el[j],     0.f);
            float by0 = fmaxf(ry + b_el[j + 1], 0.f);
            float lx = 0.f, ly = 0.f;
            #pragma unroll
            for (int p = 0; p < 8; p++) { lx += slr[p][jq].x; ly += slr[p][jq].y; }
            lx += b_res[j]; ly += b_res[j + 1];
            float cs = 0.5f / (1.0f + expf(-cnn_gain[0]));
            float ss = 0.4f / (1.0f + expf(-sconv_gain[0]));
            r.x = fmaxf(bx0 + cs * lx + ss * b_proj[j],     0.f);
            r.y = fmaxf(by0 + cs * ly + ss * b_proj[j + 1], 0.f);
        }
        *(float2*)&out[b * 1536 + branch * 512 + j] = r;
    }
}

// ---------------------------------------------------------------------------
extern "C" void kernel_launch(void* const* d_in, const int* in_sizes, int n_in,
                              void* d_out, int out_size)
{
    const float* distance   = (const float*)d_in[0];
    const float* azimuth    = (const float*)d_in[1];
    const float* elevation  = (const float*)d_in[2];
    const float* rspikes    = (const float*)d_in[3];
    const float* W_dist     = (const float*)d_in[4];
    const float* b_dist     = (const float*)d_in[5];
    const float* W_az       = (const float*)d_in[6];
    const float* b_az       = (const float*)d_in[7];
    const float* W_el       = (const float*)d_in[8];
    const float* b_el       = (const float*)d_in[9];
    const float* conv1_w    = (const float*)d_in[10];
    const float* conv1_b    = (const float*)d_in[11];
    const float* conv2_w    = (const float*)d_in[12];
    const float* conv2_b    = (const float*)d_in[13];
    const float* W_res      = (const float*)d_in[14];
    const float* b_res      = (const float*)d_in[15];
    const float* b_proj     = (const float*)d_in[19];
    const float* cnn_gain   = (const float*)d_in[20];
    const float* sconv_gain = (const float*)d_in[21];

    cudaFuncSetAttribute(conv_fused_kernel,
                         cudaFuncAttributeMaxDynamicSharedMemorySize, SMEM_BYTES);

    dim3 gconv(GX, GY, BATCH);
    conv_fused_kernel<<<gconv, 512, SMEM_BYTES>>>(rspikes, conv1_w, conv1_b,
                                                  conv2_w, conv2_b);

    dim3 ghead(24, BATCH);
    head_kernel<<<ghead, 256>>>(distance, azimuth, elevation,
                                W_dist, b_dist, W_az, b_az, W_el, b_el,
                                W_res, b_res, b_proj, cnn_gain, sconv_gain,
                                (float*)d_out);
}

// round 14
// speedup vs baseline: 1.4433x; 1.1706x over previous
#include <cuda_runtime.h>
#include <math.h>
#include <stdint.h>

// ---------------------------------------------------------------------------
// CombinedElevationEncoder — both convs on bf16 m16n8k16 mma.sync.
//
// Insight 1: dual-CNN branch only consumed through (4,4) block-mean pool ->
//            fuse conv1+relu+conv2+relu+pool; activations never touch GMEM.
// Insight 2: spiking LSTM emits spike(mem-1), mem = sig(o)*tanh(syn) <= 1
//            -> all spikes exactly 0 -> sconv_res == b_proj; scan skipped.
// R14: (a) conv2 adjacent-row streaming: warp owns out rows (2wid, 2wid+1);
//     conv1-row fragments loaded once, shared by both rows' chains
//     (576 -> 384 LDS/warp). (b) head processes 2 batches per block
//     (halves W re-read L2 traffic). conv1 = R13 row-pair units.
// ---------------------------------------------------------------------------

#define BATCH 32
#define HH    128
#define WW    1536
#define TH    32
#define TW    128
#define GX    (WW / TW)  // 12
#define GY    (HH / TH)  // 4
#define NCONTRIB 3       // (32/TH)*(384/TW) = 1*3

#define IN_ROWS 38       // 32 out rows + 2 (conv2) + 4 (conv1) halo
#define IN_STR  160      // input tile cols (bf16x2 words); quad-aligned
#define C1_ROWS 34       // conv1 rows needed: out rows -1..+32
#define C1_STR  144      // conv1 plane cols (9 chunks of 16)
#define N_UNITS 153      // conv1 row-pair units: 9 strips * 17 pairs

// dynamic smem word offsets
#define OFF_INB 0                          // 38*160 = 6080
#define OFF_C1  6080                       // 34*144*4 = 19584
#define OFF_W1B 25664                      // 320
#define OFF_W2B 25984                      // 576
#define OFF_B1  26560
#define OFF_B2  26568
#define OFF_RED 26576                      // 128
#define SMEM_WORDS 26704
#define SMEM_BYTES (SMEM_WORDS * 4)        // 106816

// partial pooled sums: [b][oc][ph][pw][contrib]
__device__ float g_partial[BATCH * 8 * 4 * 4 * NCONTRIB];

// pack two fp32 -> bf16x2 (lo = first arg)
__device__ __forceinline__ uint32_t bfpack(float lo, float hi) {
    uint32_t d;
    asm("cvt.rn.bf16x2.f32 %0, %1, %2;" : "=r"(d) : "f"(hi), "f"(lo));
    return d;
}

// m16n8k16 bf16 mma, accumulate in place (fp32 accum)
__device__ __forceinline__ void mma_bf16(float& c0, float& c1, float& c2, float& c3,
                                         uint32_t a0, uint32_t a1, uint32_t a2, uint32_t a3,
                                         uint32_t b0, uint32_t b1) {
    asm volatile(
        "mma.sync.aligned.m16n8k16.row.col.f32.bf16.bf16.f32 "
        "{%0,%1,%2,%3}, {%4,%5,%6,%7}, {%8,%9}, {%0,%1,%2,%3};"
        : "+f"(c0), "+f"(c1), "+f"(c2), "+f"(c3)
        : "r"(a0), "r"(a1), "r"(a2), "r"(a3), "r"(b0), "r"(b1));
}

// ---------------------------------------------------------------------------
__global__ __launch_bounds__(512, 2)
void conv_fused_kernel(const float* __restrict__ x,      // [B,2,H,W]
                       const float* __restrict__ w1,     // [8,2,5,7]
                       const float* __restrict__ b1,     // [8]
                       const float* __restrict__ w2,     // [8,8,3,5]
                       const float* __restrict__ b2)     // [8]
{
    extern __shared__ __align__(16) uint32_t dsm[];
    uint32_t* sInB = dsm + OFF_INB;   // [row38][col160] bf16x2 (ic0,ic1)
    uint32_t* sC1  = dsm + OFF_C1;    // [pos=row*144+c][4 words: tig -> oc 2tig,2tig+1]
    uint32_t* sW1B = dsm + OFF_W1B;   // [(kh*8+kw)*8+oc]
    uint32_t* sW2B = dsm + OFF_W2B;   // [((kh*6+kw)*4+tg)*8+oc]
    float* sB1s = (float*)(dsm + OFF_B1);
    float* sB2s = (float*)(dsm + OFF_B2);
    float* sRed = (float*)(dsm + OFF_RED);

    const int tid = threadIdx.x;
    const int wid = tid >> 5;
    const int lid = tid & 31;
    const int g   = lid >> 2;     // fragment group
    const int tig = lid & 3;      // thread in group
    const int bx = blockIdx.x, by = blockIdx.y, b = blockIdx.z;
    const int h0 = by * TH - 3;
    const int w0 = bx * TW - 8;   // 4-aligned tile origin (input word col +3 shift)

    // ---- build weight tables ----
    for (int idx = tid; idx < 320; idx += 512) {
        int oc = idx & 7; int t = idx >> 3;
        int kw = t & 7; int kh = t >> 3;
        float lo = 0.f, hi = 0.f;
        if (kw < 7) {
            lo = w1[((oc * 2 + 0) * 5 + kh) * 7 + kw];
            hi = w1[((oc * 2 + 1) * 5 + kh) * 7 + kw];
        }
        sW1B[idx] = bfpack(lo, hi);
    }
    for (int idx = tid; idx < 576; idx += 512) {
        int oc = idx & 7; int t = idx >> 3;
        int tg = t & 3; t >>= 2;
        int kw = t % 6; int kh = t / 6;
        float lo = 0.f, hi = 0.f;
        if (kw < 5) {
            lo = w2[((oc * 8 + 2 * tg)     * 3 + kh) * 5 + kw];
            hi = w2[((oc * 8 + 2 * tg + 1) * 3 + kh) * 5 + kw];
        }
        sW2B[idx] = bfpack(lo, hi);
    }
    if (tid < 8) { sB1s[tid] = b1[tid]; sB2s[tid] = b2[tid]; }

    // ---- load input tile: aligned float4 quads, ic-interleaved bf16 ----
    {
        const float* p0 = x + (size_t)b * 2 * HH * WW;
        const float* p1 = p0 + HH * WW;
        for (int idx = tid; idx < IN_ROWS * 40; idx += 512) {
            int cq = idx % 40, row = idx / 40;
            int gh = h0 + row;
            int gw = w0 + cq * 4;
            float4 v0 = make_float4(0.f, 0.f, 0.f, 0.f);
            float4 v1 = v0;
            if (gh >= 0 && gh < HH && gw >= 0 && gw + 3 < WW) {
                v0 = *(const float4*)&p0[gh * WW + gw];
                v1 = *(const float4*)&p1[gh * WW + gw];
            }
            uint4 wv;
            wv.x = bfpack(v0.x, v1.x);
            wv.y = bfpack(v0.y, v1.y);
            wv.z = bfpack(v0.z, v1.z);
            wv.w = bfpack(v0.w, v1.w);
            *(uint4*)&sInB[row * IN_STR + cq * 4] = wv;
        }
    }
    __syncthreads();

    // ---- conv1 via mma: 153 row-pair units (9 strips x 17 pairs) ----
    {
        uint32_t bf[10];
        #pragma unroll
        for (int kh = 0; kh < 5; kh++) {
            bf[kh * 2]     = sW1B[(kh * 8 + tig)     * 8 + g];
            bf[kh * 2 + 1] = sW1B[(kh * 8 + tig + 4) * 8 + g];
        }
        const float bi0 = sB1s[2 * tig], bi1 = sB1s[2 * tig + 1];

        for (int u = wid; u < N_UNITS; u += 16) {
            const int s  = u / 17;
            const int r0 = (u % 17) * 2;
            const int ci = s * 16 + 3;          // input word base (+3 shift)

            uint32_t f[6][4];
            #pragma unroll
            for (int rr = 0; rr < 6; rr++) {
                const uint32_t* q = &sInB[(r0 + rr) * IN_STR + ci];
                f[rr][0] = q[g + tig];            // m=g,   kw=tig
                f[rr][1] = q[g + 8 + tig];        // m=g+8
                f[rr][2] = q[g + tig + 4];        // kw=tig+4
                f[rr][3] = q[g + 8 + tig + 4];
            }

            #pragma unroll
            for (int cr = 0; cr < 2; cr++) {
                float d0 = bi0, d1 = bi1, d2 = bi0, d3 = bi1;
                #pragma unroll
                for (int kh = 0; kh < 5; kh++)
                    mma_bf16(d0, d1, d2, d3,
                             f[cr + kh][0], f[cr + kh][1],
                             f[cr + kh][2], f[cr + kh][3],
                             bf[kh * 2], bf[kh * 2 + 1]);
                const int pos = (r0 + cr) * C1_STR + s * 16;
                sC1[(pos + g)     * 4 + tig] = bfpack(fmaxf(d0, 0.f), fmaxf(d1, 0.f));
                sC1[(pos + g + 8) * 4 + tig] = bfpack(fmaxf(d2, 0.f), fmaxf(d3, 0.f));
            }
        }
    }
    __syncthreads();

    // ---- conv2 via mma + pool: warp = out rows (2wid, 2wid+1); streaming ----
    // conv1-row fragments (12 words) loaded ONCE, feed acc_A (kh=cr) and
    // acc_B (kh=cr-1). Per-accumulator MMA order identical to R13.
    {
        uint32_t bf[18];
        #pragma unroll
        for (int kh = 0; kh < 3; kh++)
            #pragma unroll
            for (int kw6 = 0; kw6 < 6; kw6++)
                bf[kh * 6 + kw6] = sW2B[((kh * 6 + kw6) * 4 + tig) * 8 + g];
        const float bi0 = sB2s[2 * tig], bi1 = sB2s[2 * tig + 1];
        const int row0 = 2 * wid;           // out rows row0, row0+1

        float s0 = 0.f, s1 = 0.f;
        #pragma unroll
        for (int ch = 0; ch < 8; ch++) {
            const int c0 = ch * 16;
            float a0 = bi0, a1 = bi1, a2 = bi0, a3 = bi1;   // acc row0
            float e0 = bi0, e1 = bi1, e2 = bi0, e3 = bi1;   // acc row0+1
            #pragma unroll
            for (int cr = 0; cr < 4; cr++) {
                // fragment words of sC1 row (row0+cr): pos c0+g+{0..5}, +8{0..5}
                const uint32_t* pp = &sC1[((row0 + cr) * C1_STR + c0 + g) * 4];
                uint32_t fl[6], fh[6];
                #pragma unroll
                for (int k = 0; k < 6; k++) {
                    fl[k] = pp[k * 4 + tig];
                    fh[k] = pp[(k + 8) * 4 + tig];
                }
                if (cr <= 2) {       // row0, kh = cr
                    #pragma unroll
                    for (int j = 0; j < 3; j++)
                        mma_bf16(a0, a1, a2, a3,
                                 fl[2 * j], fh[2 * j], fl[2 * j + 1], fh[2 * j + 1],
                                 bf[cr * 6 + 2 * j], bf[cr * 6 + 2 * j + 1]);
                }
                if (cr >= 1) {       // row0+1, kh = cr-1
                    #pragma unroll
                    for (int j = 0; j < 3; j++)
                        mma_bf16(e0, e1, e2, e3,
                                 fl[2 * j], fh[2 * j], fl[2 * j + 1], fh[2 * j + 1],
                                 bf[(cr - 1) * 6 + 2 * j], bf[(cr - 1) * 6 + 2 * j + 1]);
                }
            }
            s0 += fmaxf(a0, 0.f) + fmaxf(a2, 0.f) + fmaxf(e0, 0.f) + fmaxf(e2, 0.f);
            s1 += fmaxf(a1, 0.f) + fmaxf(a3, 0.f) + fmaxf(e1, 0.f) + fmaxf(e3, 0.f);
        }
        // reduce over g (lane bits 2..4); s0 = oc 2tig, s1 = oc 2tig+1
        #pragma unroll
        for (int off = 4; off <= 16; off <<= 1) {
            s0 += __shfl_xor_sync(0xffffffffu, s0, off);
            s1 += __shfl_xor_sync(0xffffffffu, s1, off);
        }
        if (lid < 4) {
            sRed[wid * 8 + 2 * tig]     = s0;
            sRed[wid * 8 + 2 * tig + 1] = s1;
        }
    }
    __syncthreads();

    // deterministic partial write: one fixed slot per block (no atomics)
    if (tid < 8) {
        float t = 0.f;
        #pragma unroll
        for (int wz = 0; wz < 16; wz++) t += sRed[wz * 8 + tid];
        const int ph = by;                          // 1 row-tile per pool cell
        const int pw = bx / 3,  subx = bx - pw * 3; // 3 col-tiles per pool cell
        g_partial[(((b * 8 + tid) * 4 + ph) * 4 + pw) * NCONTRIB + subx] = t;
    }
}

// ---------------------------------------------------------------------------
// Head: grid (24, 16). Each block handles batches (by, by+16) per W load.
// seg -> branch (seg>>3) and 64-col segment (seg&7). 256 thr = 8 ks x 32 jq.
// ---------------------------------------------------------------------------
__global__ __launch_bounds__(256)
void head_kernel(const float* __restrict__ distance,
                 const float* __restrict__ azimuth,
                 const float* __restrict__ elevation,
                 const float* __restrict__ W_dist, const float* __restrict__ b_dist,
                 const float* __restrict__ W_az,   const float* __restrict__ b_az,
                 const float* __restrict__ W_el,   const float* __restrict__ b_el,
                 const float* __restrict__ W_res,  const float* __restrict__ b_res,
                 const float* __restrict__ b_proj,
                 const float* __restrict__ cnn_gain,
                 const float* __restrict__ sconv_gain,
                 float* __restrict__ out)
{
    __shared__ float sv[2][256];
    __shared__ float sp[2][128];
    __shared__ float2 sacc[2][8][32];
    __shared__ float2 slr[2][8][32];

    const int tid = threadIdx.x;
    const int jq  = tid & 31;
    const int ks  = tid >> 5;          // 0..7
    const int b0  = blockIdx.y;        // batches b0, b0+16
    const int seg = blockIdx.x;        // 0..23
    const int branch = seg >> 3;       // uniform per block
    const int j = (seg & 7) * 64 + jq * 2;   // col within 512

    const float* vec = (branch == 0) ? distance : (branch == 1) ? azimuth : elevation;
    sv[0][tid] = vec[b0 * 256 + tid];
    sv[1][tid] = vec[(b0 + 16) * 256 + tid];

    if (branch == 2 && tid < 128) {
        #pragma unroll
        for (int q = 0; q < 2; q++) {
            const float* pp = g_partial + ((b0 + q * 16) * 128 + tid) * NCONTRIB;
            float t = 0.f;
            #pragma unroll
            for (int i = 0; i < NCONTRIB; i++) t += pp[i];
            sp[q][tid] = t * (1.0f / (32.0f * 384.0f));
        }
    }
    __syncthreads();

    const float* Wm = (branch == 0) ? W_dist : (branch == 1) ? W_az : W_el;
    float2 acc0 = make_float2(0.f, 0.f), acc1 = acc0;
    #pragma unroll 8
    for (int k = ks * 32; k < ks * 32 + 32; k++) {
        float2 w = *(const float2*)&Wm[k * 512 + j];
        float u0 = sv[0][k], u1 = sv[1][k];
        acc0.x = fmaf(u0, w.x, acc0.x);
        acc0.y = fmaf(u0, w.y, acc0.y);
        acc1.x = fmaf(u1, w.x, acc1.x);
        acc1.y = fmaf(u1, w.y, acc1.y);
    }
    sacc[0][ks][jq] = acc0;
    sacc[1][ks][jq] = acc1;

    if (branch == 2) {
        float2 lr0 = make_float2(0.f, 0.f), lr1 = lr0;
        #pragma unroll 8
        for (int k = ks * 16; k < ks * 16 + 16; k++) {
            float2 w = *(const float2*)&W_res[k * 512 + j];
            float u0 = sp[0][k], u1 = sp[1][k];
            lr0.x = fmaf(u0, w.x, lr0.x);
            lr0.y = fmaf(u0, w.y, lr0.y);
            lr1.x = fmaf(u1, w.x, lr1.x);
            lr1.y = fmaf(u1, w.y, lr1.y);
        }
        slr[0][ks][jq] = lr0;
        slr[1][ks][jq] = lr1;
    }
    __syncthreads();

    if (ks < 2) {                      // ks = batch selector (0 -> b0, 1 -> b0+16)
        const int q = ks;
        const int b = b0 + q * 16;
        float rx = 0.f, ry = 0.f;
        #pragma unroll
        for (int p = 0; p < 8; p++) { rx += sacc[q][p][jq].x; ry += sacc[q][p][jq].y; }

        float2 r;
        if (branch == 0) {
            r.x = fmaxf(rx + b_dist[j],     0.f);
            r.y = fmaxf(ry + b_dist[j + 1], 0.f);
        } else if (branch == 1) {
            r.x = fmaxf(rx + b_az[j],     0.f);
            r.y = fmaxf(ry + b_az[j + 1], 0.f);
        } else {
            float bx0 = fmaxf(rx + b_el[j],     0.f);
            float by0 = fmaxf(ry + b_el[j + 1], 0.f);
            float lx = 0.f, ly = 0.f;
            #pragma unroll
            for (int p = 0; p < 8; p++) { lx += slr[q][p][jq].x; ly += slr[q][p][jq].y; }
            lx += b_res[j]; ly += b_res[j + 1];
            float cs = 0.5f / (1.0f + expf(-cnn_gain[0]));
            float ss = 0.4f / (1.0f + expf(-sconv_gain[0]));
            r.x = fmaxf(bx0 + cs * lx + ss * b_proj[j],     0.f);
            r.y = fmaxf(by0 + cs * ly + ss * b_proj[j + 1], 0.f);
        }
        *(float2*)&out[b * 1536 + branch * 512 + j] = r;
    }
}

// ---------------------------------------------------------------------------
extern "C" void kernel_launch(void* const* d_in, const int* in_sizes, int n_in,
                              void* d_out, int out_size)
{
    const float* distance   = (const float*)d_in[0];
    const float* azimuth    = (const float*)d_in[1];
    const float* elevation  = (const float*)d_in[2];
    const float* rspikes    = (const float*)d_in[3];
    const float* W_dist     = (const float*)d_in[4];
    const float* b_dist     = (const float*)d_in[5];
    const float* W_az       = (const float*)d_in[6];
    const float* b_az       = (const float*)d_in[7];
    const float* W_el       = (const float*)d_in[8];
    const float* b_el       = (const float*)d_in[9];
    const float* conv1_w    = (const float*)d_in[10];
    const float* conv1_b    = (const float*)d_in[11];
    const float* conv2_w    = (const float*)d_in[12];
    const float* conv2_b    = (const float*)d_in[13];
    const float* W_res      = (const float*)d_in[14];
    const float* b_res      = (const float*)d_in[15];
    const float* b_proj     = (const float*)d_in[19];
    const float* cnn_gain   = (const float*)d_in[20];
    const float* sconv_gain = (const float*)d_in[21];

    cudaFuncSetAttribute(conv_fused_kernel,
                         cudaFuncAttributeMaxDynamicSharedMemorySize, SMEM_BYTES);

    dim3 gconv(GX, GY, BATCH);
    conv_fused_kernel<<<gconv, 512, SMEM_BYTES>>>(rspikes, conv1_w, conv1_b,
                                                  conv2_w, conv2_b);

    dim3 ghead(24, 16);
    head_kernel<<<ghead, 256>>>(distance, azimuth, elevation,
                                W_dist, b_dist, W_az, b_az, W_el, b_el,
                                W_res, b_res, b_proj, cnn_gain, sconv_gain,
                                (float*)d_out);
}

// round 15
// speedup vs baseline: 1.5227x; 1.0550x over previous
#include <cuda_runtime.h>
#include <math.h>
#include <stdint.h>

// ---------------------------------------------------------------------------
// CombinedElevationEncoder — both convs on bf16 m16n8k16 mma.sync.
//
// Insight 1: dual-CNN branch only consumed through (4,4) block-mean pool ->
//            fuse conv1+relu+conv2+relu+pool; activations never touch GMEM.
// Insight 2: spiking LSTM emits spike(mem-1), mem = sig(o)*tanh(syn) <= 1
//            -> all spikes exactly 0 -> sconv_res == b_proj; scan skipped.
// R15: (a) conv1 rolling-window row-quads (8 LDS/chunk vs 12): 72 quad units
//     + 9 pair units. (b) head reverted to R13 (768-block 8-way k-split;
//     R14's 2-batch head regressed occupancy). conv2 = R14 streaming.
// ---------------------------------------------------------------------------

#define BATCH 32
#define HH    128
#define WW    1536
#define TH    32
#define TW    128
#define GX    (WW / TW)  // 12
#define GY    (HH / TH)  // 4
#define NCONTRIB 3       // (32/TH)*(384/TW) = 1*3

#define IN_ROWS 38       // 32 out rows + 2 (conv2) + 4 (conv1) halo
#define IN_STR  160      // input tile cols (bf16x2 words); quad-aligned
#define C1_ROWS 34       // conv1 rows needed: out rows -1..+32
#define C1_STR  144      // conv1 plane cols (9 chunks of 16)

// dynamic smem word offsets
#define OFF_INB 0                          // 38*160 = 6080
#define OFF_C1  6080                       // 34*144*4 = 19584
#define OFF_W1B 25664                      // 320
#define OFF_W2B 25984                      // 576
#define OFF_B1  26560
#define OFF_B2  26568
#define OFF_RED 26576                      // 128
#define SMEM_WORDS 26704
#define SMEM_BYTES (SMEM_WORDS * 4)        // 106816

// partial pooled sums: [b][oc][ph][pw][contrib]
__device__ float g_partial[BATCH * 8 * 4 * 4 * NCONTRIB];

// pack two fp32 -> bf16x2 (lo = first arg)
__device__ __forceinline__ uint32_t bfpack(float lo, float hi) {
    uint32_t d;
    asm("cvt.rn.bf16x2.f32 %0, %1, %2;" : "=r"(d) : "f"(hi), "f"(lo));
    return d;
}

// m16n8k16 bf16 mma, accumulate in place (fp32 accum)
__device__ __forceinline__ void mma_bf16(float& c0, float& c1, float& c2, float& c3,
                                         uint32_t a0, uint32_t a1, uint32_t a2, uint32_t a3,
                                         uint32_t b0, uint32_t b1) {
    asm volatile(
        "mma.sync.aligned.m16n8k16.row.col.f32.bf16.bf16.f32 "
        "{%0,%1,%2,%3}, {%4,%5,%6,%7}, {%8,%9}, {%0,%1,%2,%3};"
        : "+f"(c0), "+f"(c1), "+f"(c2), "+f"(c3)
        : "r"(a0), "r"(a1), "r"(a2), "r"(a3), "r"(b0), "r"(b1));
}

// ---------------------------------------------------------------------------
__global__ __launch_bounds__(512, 2)
void conv_fused_kernel(const float* __restrict__ x,      // [B,2,H,W]
                       const float* __restrict__ w1,     // [8,2,5,7]
                       const float* __restrict__ b1,     // [8]
                       const float* __restrict__ w2,     // [8,8,3,5]
                       const float* __restrict__ b2)     // [8]
{
    extern __shared__ __align__(16) uint32_t dsm[];
    uint32_t* sInB = dsm + OFF_INB;   // [row38][col160] bf16x2 (ic0,ic1)
    uint32_t* sC1  = dsm + OFF_C1;    // [pos=row*144+c][4 words: tig -> oc 2tig,2tig+1]
    uint32_t* sW1B = dsm + OFF_W1B;   // [(kh*8+kw)*8+oc]
    uint32_t* sW2B = dsm + OFF_W2B;   // [((kh*6+kw)*4+tg)*8+oc]
    float* sB1s = (float*)(dsm + OFF_B1);
    float* sB2s = (float*)(dsm + OFF_B2);
    float* sRed = (float*)(dsm + OFF_RED);

    const int tid = threadIdx.x;
    const int wid = tid >> 5;
    const int lid = tid & 31;
    const int g   = lid >> 2;     // fragment group
    const int tig = lid & 3;      // thread in group
    const int bx = blockIdx.x, by = blockIdx.y, b = blockIdx.z;
    const int h0 = by * TH - 3;
    const int w0 = bx * TW - 8;   // 4-aligned tile origin (input word col +3 shift)

    // ---- build weight tables ----
    for (int idx = tid; idx < 320; idx += 512) {
        int oc = idx & 7; int t = idx >> 3;
        int kw = t & 7; int kh = t >> 3;
        float lo = 0.f, hi = 0.f;
        if (kw < 7) {
            lo = w1[((oc * 2 + 0) * 5 + kh) * 7 + kw];
            hi = w1[((oc * 2 + 1) * 5 + kh) * 7 + kw];
        }
        sW1B[idx] = bfpack(lo, hi);
    }
    for (int idx = tid; idx < 576; idx += 512) {
        int oc = idx & 7; int t = idx >> 3;
        int tg = t & 3; t >>= 2;
        int kw = t % 6; int kh = t / 6;
        float lo = 0.f, hi = 0.f;
        if (kw < 5) {
            lo = w2[((oc * 8 + 2 * tg)     * 3 + kh) * 5 + kw];
            hi = w2[((oc * 8 + 2 * tg + 1) * 3 + kh) * 5 + kw];
        }
        sW2B[idx] = bfpack(lo, hi);
    }
    if (tid < 8) { sB1s[tid] = b1[tid]; sB2s[tid] = b2[tid]; }

    // ---- load input tile: aligned float4 quads, ic-interleaved bf16 ----
    {
        const float* p0 = x + (size_t)b * 2 * HH * WW;
        const float* p1 = p0 + HH * WW;
        for (int idx = tid; idx < IN_ROWS * 40; idx += 512) {
            int cq = idx % 40, row = idx / 40;
            int gh = h0 + row;
            int gw = w0 + cq * 4;
            float4 v0 = make_float4(0.f, 0.f, 0.f, 0.f);
            float4 v1 = v0;
            if (gh >= 0 && gh < HH && gw >= 0 && gw + 3 < WW) {
                v0 = *(const float4*)&p0[gh * WW + gw];
                v1 = *(const float4*)&p1[gh * WW + gw];
            }
            uint4 wv;
            wv.x = bfpack(v0.x, v1.x);
            wv.y = bfpack(v0.y, v1.y);
            wv.z = bfpack(v0.z, v1.z);
            wv.w = bfpack(v0.w, v1.w);
            *(uint4*)&sInB[row * IN_STR + cq * 4] = wv;
        }
    }
    __syncthreads();

    // ---- conv1 via mma: 72 rolling-window quad units (rows 0..31/strip) ----
    // unit = (strip s, rows 4t..4t+3); fragment window of 5 rows, 3 reloads.
    {
        uint32_t bf[10];
        #pragma unroll
        for (int kh = 0; kh < 5; kh++) {
            bf[kh * 2]     = sW1B[(kh * 8 + tig)     * 8 + g];
            bf[kh * 2 + 1] = sW1B[(kh * 8 + tig + 4) * 8 + g];
        }
        const float bi0 = sB1s[2 * tig], bi1 = sB1s[2 * tig + 1];

        for (int u = wid; u < 72; u += 16) {
            const int s  = u >> 3;
            const int r0 = (u & 7) * 4;
            const int ci = s * 16 + 3;          // input word base (+3 shift)

            uint32_t f[5][4];
            #pragma unroll
            for (int rr = 0; rr < 5; rr++) {
                const uint32_t* q = &sInB[(r0 + rr) * IN_STR + ci];
                f[rr][0] = q[g + tig];            // m=g,   kw=tig
                f[rr][1] = q[g + 8 + tig];        // m=g+8
                f[rr][2] = q[g + tig + 4];        // kw=tig+4
                f[rr][3] = q[g + 8 + tig + 4];
            }

            #pragma unroll
            for (int cr = 0; cr < 4; cr++) {
                float d0 = bi0, d1 = bi1, d2 = bi0, d3 = bi1;
                #pragma unroll
                for (int kh = 0; kh < 5; kh++) {
                    const int w = (cr + kh) % 5;
                    mma_bf16(d0, d1, d2, d3,
                             f[w][0], f[w][1], f[w][2], f[w][3],
                             bf[kh * 2], bf[kh * 2 + 1]);
                }
                const int pos = (r0 + cr) * C1_STR + s * 16;
                sC1[(pos + g)     * 4 + tig] = bfpack(fmaxf(d0, 0.f), fmaxf(d1, 0.f));
                sC1[(pos + g + 8) * 4 + tig] = bfpack(fmaxf(d2, 0.f), fmaxf(d3, 0.f));
                if (cr < 3) {                     // reload window slot cr <- row r0+5+cr
                    const uint32_t* q = &sInB[(r0 + 5 + cr) * IN_STR + ci];
                    f[cr][0] = q[g + tig];
                    f[cr][1] = q[g + 8 + tig];
                    f[cr][2] = q[g + tig + 4];
                    f[cr][3] = q[g + 8 + tig + 4];
                }
            }
        }
    }
    // ---- conv1 pair units: rows 32,33 of each strip (9 units, warps 0..8) ----
    if (wid < 9) {
        uint32_t bf[10];
        #pragma unroll
        for (int kh = 0; kh < 5; kh++) {
            bf[kh * 2]     = sW1B[(kh * 8 + tig)     * 8 + g];
            bf[kh * 2 + 1] = sW1B[(kh * 8 + tig + 4) * 8 + g];
        }
        const float bi0 = sB1s[2 * tig], bi1 = sB1s[2 * tig + 1];
        const int s  = wid;
        const int r0 = 32;
        const int ci = s * 16 + 3;

        uint32_t f[6][4];
        #pragma unroll
        for (int rr = 0; rr < 6; rr++) {
            const uint32_t* q = &sInB[(r0 + rr) * IN_STR + ci];
            f[rr][0] = q[g + tig];
            f[rr][1] = q[g + 8 + tig];
            f[rr][2] = q[g + tig + 4];
            f[rr][3] = q[g + 8 + tig + 4];
        }
        #pragma unroll
        for (int cr = 0; cr < 2; cr++) {
            float d0 = bi0, d1 = bi1, d2 = bi0, d3 = bi1;
            #pragma unroll
            for (int kh = 0; kh < 5; kh++)
                mma_bf16(d0, d1, d2, d3,
                         f[cr + kh][0], f[cr + kh][1],
                         f[cr + kh][2], f[cr + kh][3],
                         bf[kh * 2], bf[kh * 2 + 1]);
            const int pos = (r0 + cr) * C1_STR + s * 16;
            sC1[(pos + g)     * 4 + tig] = bfpack(fmaxf(d0, 0.f), fmaxf(d1, 0.f));
            sC1[(pos + g + 8) * 4 + tig] = bfpack(fmaxf(d2, 0.f), fmaxf(d3, 0.f));
        }
    }
    __syncthreads();

    // ---- conv2 via mma + pool: warp = out rows (2wid, 2wid+1); streaming ----
    {
        uint32_t bf[18];
        #pragma unroll
        for (int kh = 0; kh < 3; kh++)
            #pragma unroll
            for (int kw6 = 0; kw6 < 6; kw6++)
                bf[kh * 6 + kw6] = sW2B[((kh * 6 + kw6) * 4 + tig) * 8 + g];
        const float bi0 = sB2s[2 * tig], bi1 = sB2s[2 * tig + 1];
        const int row0 = 2 * wid;           // out rows row0, row0+1

        float s0 = 0.f, s1 = 0.f;
        #pragma unroll
        for (int ch = 0; ch < 8; ch++) {
            const int c0 = ch * 16;
            float a0 = bi0, a1 = bi1, a2 = bi0, a3 = bi1;   // acc row0
            float e0 = bi0, e1 = bi1, e2 = bi0, e3 = bi1;   // acc row0+1
            #pragma unroll
            for (int cr = 0; cr < 4; cr++) {
                const uint32_t* pp = &sC1[((row0 + cr) * C1_STR + c0 + g) * 4];
                uint32_t fl[6], fh[6];
                #pragma unroll
                for (int k = 0; k < 6; k++) {
                    fl[k] = pp[k * 4 + tig];
                    fh[k] = pp[(k + 8) * 4 + tig];
                }
                if (cr <= 2) {       // row0, kh = cr
                    #pragma unroll
                    for (int j = 0; j < 3; j++)
                        mma_bf16(a0, a1, a2, a3,
                                 fl[2 * j], fh[2 * j], fl[2 * j + 1], fh[2 * j + 1],
                                 bf[cr * 6 + 2 * j], bf[cr * 6 + 2 * j + 1]);
                }
                if (cr >= 1) {       // row0+1, kh = cr-1
                    #pragma unroll
                    for (int j = 0; j < 3; j++)
                        mma_bf16(e0, e1, e2, e3,
                                 fl[2 * j], fh[2 * j], fl[2 * j + 1], fh[2 * j + 1],
                                 bf[(cr - 1) * 6 + 2 * j], bf[(cr - 1) * 6 + 2 * j + 1]);
                }
            }
            s0 += fmaxf(a0, 0.f) + fmaxf(a2, 0.f) + fmaxf(e0, 0.f) + fmaxf(e2, 0.f);
            s1 += fmaxf(a1, 0.f) + fmaxf(a3, 0.f) + fmaxf(e1, 0.f) + fmaxf(e3, 0.f);
        }
        // reduce over g (lane bits 2..4); s0 = oc 2tig, s1 = oc 2tig+1
        #pragma unroll
        for (int off = 4; off <= 16; off <<= 1) {
            s0 += __shfl_xor_sync(0xffffffffu, s0, off);
            s1 += __shfl_xor_sync(0xffffffffu, s1, off);
        }
        if (lid < 4) {
            sRed[wid * 8 + 2 * tig]     = s0;
            sRed[wid * 8 + 2 * tig + 1] = s1;
        }
    }
    __syncthreads();

    // deterministic partial write: one fixed slot per block (no atomics)
    if (tid < 8) {
        float t = 0.f;
        #pragma unroll
        for (int wz = 0; wz < 16; wz++) t += sRed[wz * 8 + tid];
        const int ph = by;                          // 1 row-tile per pool cell
        const int pw = bx / 3,  subx = bx - pw * 3; // 3 col-tiles per pool cell
        g_partial[(((b * 8 + tid) * 4 + ph) * 4 + pw) * NCONTRIB + subx] = t;
    }
}

// ---------------------------------------------------------------------------
// Head: grid (24, 32). seg -> branch (seg>>3) and 64-col segment (seg&7).
// 256 thr = 8 ks x 32 jq; jq owns 2 cols. sconv branch == b_proj.
// ---------------------------------------------------------------------------
__global__ __launch_bounds__(256)
void head_kernel(const float* __restrict__ distance,
                 const float* __restrict__ azimuth,
                 const float* __restrict__ elevation,
                 const float* __restrict__ W_dist, const float* __restrict__ b_dist,
                 const float* __restrict__ W_az,   const float* __restrict__ b_az,
                 const float* __restrict__ W_el,   const float* __restrict__ b_el,
                 const float* __restrict__ W_res,  const float* __restrict__ b_res,
                 const float* __restrict__ b_proj,
                 const float* __restrict__ cnn_gain,
                 const float* __restrict__ sconv_gain,
                 float* __restrict__ out)
{
    __shared__ float sv[256];
    __shared__ float sp[128];
    __shared__ float2 sacc[8][32];
    __shared__ float2 slr[8][32];

    const int tid = threadIdx.x;
    const int jq  = tid & 31;
    const int ks  = tid >> 5;          // 0..7
    const int b   = blockIdx.y;
    const int seg = blockIdx.x;        // 0..23
    const int branch = seg >> 3;       // uniform per block
    const int j = (seg & 7) * 64 + jq * 2;   // col within 512

    const float* vec = (branch == 0) ? distance : (branch == 1) ? azimuth : elevation;
    sv[tid] = vec[b * 256 + tid];

    if (branch == 2 && tid < 128) {
        const float* pp = g_partial + (b * 128 + tid) * NCONTRIB;
        float t = 0.f;
        #pragma unroll
        for (int i = 0; i < NCONTRIB; i++) t += pp[i];
        sp[tid] = t * (1.0f / (32.0f * 384.0f));
    }
    __syncthreads();

    const float* Wm = (branch == 0) ? W_dist : (branch == 1) ? W_az : W_el;
    float2 acc = make_float2(0.f, 0.f);
    #pragma unroll 8
    for (int k = ks * 32; k < ks * 32 + 32; k++) {
        float s = sv[k];
        float2 w = *(const float2*)&Wm[k * 512 + j];
        acc.x = fmaf(s, w.x, acc.x);
        acc.y = fmaf(s, w.y, acc.y);
    }
    sacc[ks][jq] = acc;

    if (branch == 2) {
        float2 lr = make_float2(0.f, 0.f);
        #pragma unroll 8
        for (int k = ks * 16; k < ks * 16 + 16; k++) {
            float s = sp[k];
            float2 w = *(const float2*)&W_res[k * 512 + j];
            lr.x = fmaf(s, w.x, lr.x);
            lr.y = fmaf(s, w.y, lr.y);
        }
        slr[ks][jq] = lr;
    }
    __syncthreads();

    if (ks == 0) {
        float rx = 0.f, ry = 0.f;
        #pragma unroll
        for (int p = 0; p < 8; p++) { rx += sacc[p][jq].x; ry += sacc[p][jq].y; }

        float2 r;
        if (branch == 0) {
            r.x = fmaxf(rx + b_dist[j],     0.f);
            r.y = fmaxf(ry + b_dist[j + 1], 0.f);
        } else if (branch == 1) {
            r.x = fmaxf(rx + b_az[j],     0.f);
            r.y = fmaxf(ry + b_az[j + 1], 0.f);
        } else {
            float bx0 = fmaxf(rx + b_el[j],     0.f);
            float by0 = fmaxf(ry + b_el[j + 1], 0.f);
            float lx = 0.f, ly = 0.f;
            #pragma unroll
            for (int p = 0; p < 8; p++) { lx += slr[p][jq].x; ly += slr[p][jq].y; }
            lx += b_res[j]; ly += b_res[j + 1];
            float cs = 0.5f / (1.0f + expf(-cnn_gain[0]));
            float ss = 0.4f / (1.0f + expf(-sconv_gain[0]));
            r.x = fmaxf(bx0 + cs * lx + ss * b_proj[j],     0.f);
            r.y = fmaxf(by0 + cs * ly + ss * b_proj[j + 1], 0.f);
        }
        *(float2*)&out[b * 1536 + branch * 512 + j] = r;
    }
}

// ---------------------------------------------------------------------------
extern "C" void kernel_launch(void* const* d_in, const int* in_sizes, int n_in,
                              void* d_out, int out_size)
{
    const float* distance   = (const float*)d_in[0];
    const float* azimuth    = (const float*)d_in[1];
    const float* elevation  = (const float*)d_in[2];
    const float* rspikes    = (const float*)d_in[3];
    const float* W_dist     = (const float*)d_in[4];
    const float* b_dist     = (const float*)d_in[5];
    const float* W_az       = (const float*)d_in[6];
    const float* b_az       = (const float*)d_in[7];
    const float* W_el       = (const float*)d_in[8];
    const float* b_el       = (const float*)d_in[9];
    const float* conv1_w    = (const float*)d_in[10];
    const float* conv1_b    = (const float*)d_in[11];
    const float* conv2_w    = (const float*)d_in[12];
    const float* conv2_b    = (const float*)d_in[13];
    const float* W_res      = (const float*)d_in[14];
    const float* b_res      = (const float*)d_in[15];
    const float* b_proj     = (const float*)d_in[19];
    const float* cnn_gain   = (const float*)d_in[20];
    const float* sconv_gain = (const float*)d_in[21];

    cudaFuncSetAttribute(conv_fused_kernel,
                         cudaFuncAttributeMaxDynamicSharedMemorySize, SMEM_BYTES);

    dim3 gconv(GX, GY, BATCH);
    conv_fused_kernel<<<gconv, 512, SMEM_BYTES>>>(rspikes, conv1_w, conv1_b,
                                                  conv2_w, conv2_b);

    dim3 ghead(24, 32);
    head_kernel<<<ghead, 256>>>(distance, azimuth, elevation,
                                W_dist, b_dist, W_az, b_az, W_el, b_el,
                                W_res, b_res, b_proj, cnn_gain, sconv_gain,
                                (float*)d_out);
}